// round 12
// baseline (speedup 1.0000x reference)
#include <cuda_runtime.h>
#include <math.h>

// ---------------------------------------------------------------------------
// RadiomicsPreservationLoss — half-warp image split + rolling pipeline.
// Lanes 0-15 process the INPUT image, lanes 16-31 the OUTPUT image over the
// same 64-col strip; per-lane rolling 3-row window is one image only
// (18 regs), enabling occupancy 4. Cross-image diffs via shfl_xor(16)
// (symmetric |a-b|, double-counted, x0.5 at reduce). Moments reduce within
// half-warps. Balanced contiguous row-runs, fused last-block finalize.
// inputs: input_img, output_img, roi_mask  [32,1,512,512] f32
// output: [intensity, texture, shape, total] (4 x f32)
// ---------------------------------------------------------------------------

#define HH 512
#define WW 512
#define BB 32
#define NBLK 592                 // 4 blocks/SM on 148 SMs
#define NTHR 256
#define NSLOTS (NBLK * 8)        // 4736 warp slots
#define RU 131072                // 256 stripcols(64w) * 512 rows
#define RUQ (RU / NSLOTS)        // 27
#define RUR (RU % NSLOTS)        // 3200
#define FULLM 0xffffffffu

__device__ double g_part[NBLK][11];
__device__ unsigned g_cnt = 0;

// Load one row of THIS lane's image as 6 values: cols cb-1 .. cb+4.
// p = lane base at (r, cb). Shuffles stay within the half-warp for interior
// sublanes; sublane 0/15 use a single predicated halo load (hload per run).
__device__ __forceinline__ void ldrow(
    float* __restrict__ R, const float* __restrict__ p, int r,
    int sub, int eo, bool hload)
{
    const bool ok = ((unsigned)r < (unsigned)HH);
    float4 q = make_float4(0.f, 0.f, 0.f, 0.f);
    if (ok) q = *(const float4*)p;
    R[0] = q.x; R[1] = q.y; R[2] = q.z; R[3] = q.w;

    float al = __shfl_up_sync(FULLM, q.w, 1);
    float ar = __shfl_down_sync(FULLM, q.x, 1);
    float hv = (hload && ok) ? p[eo] : 0.f;   // predicated: <=4 lanes/warp
    R[4] = (sub == 0)  ? hv : al;
    R[5] = (sub == 15) ? hv : ar;
}

// 3x3 variance + laplacian for 4 px from three 6-wide rows (one image).
__device__ __forceinline__ void proc6(
    const float* __restrict__ A0, const float* __restrict__ A1,
    const float* __restrict__ A2,
    float* __restrict__ var, float* __restrict__ lap)
{
    float cs[6], cq[6];
    #pragma unroll
    for (int j = 0; j < 6; j++) {
        cs[j] = A0[j] + A1[j] + A2[j];
        float u = A0[j] * A0[j];
        u = fmaf(A1[j], A1[j], u);
        cq[j] = fmaf(A2[j], A2[j], u);
    }
    const float inv9 = 1.f / 9.f;
    #pragma unroll
    for (int j = 0; j < 4; j++) {
        // row arrays are [halo_left? no: layout 0..3 own, 4 left halo, 5 right halo]
        float Sm = (j == 0) ? cs[4] : cs[j - 1];
        float Sp = (j == 3) ? cs[5] : cs[j + 1];
        float Qm = (j == 0) ? cq[4] : cq[j - 1];
        float Qp = (j == 3) ? cq[5] : cq[j + 1];
        float S = Sm + cs[j] + Sp;
        float Q = Qm + cq[j] + Qp;
        float bmn = S * inv9;
        var[j] = fmaf(-bmn, bmn, Q * inv9);
        float am = (j == 0) ? A1[4] : A1[j - 1];
        float ap = (j == 3) ? A1[5] : A1[j + 1];
        lap[j] = fmaf(-5.f, A1[j], cs[j] + am + ap);
    }
}

__global__ void __launch_bounds__(NTHR, 4) k_main(
    const float* __restrict__ g_in,
    const float* __restrict__ g_out,
    const float* __restrict__ g_mask,
    float* __restrict__ final_out)
{
    __shared__ float sred[11][8];
    __shared__ bool s_last;
    __shared__ double sacc[11];

    const int t    = threadIdx.x;
    const int lane = t & 31;
    const int wid  = t >> 5;
    const int slot = blockIdx.x * 8 + wid;   // 0..4735
    const int sub  = lane & 15;              // sublane within half-warp
    const int half = lane >> 4;              // 0: input img, 1: output img
    const int eo   = (sub == 0) ? -1 : 4;    // halo offset for edge sublanes

    float msum = 0.f, texs = 0.f, shps = 0.f;
    float p1 = 0.f, p2 = 0.f, p3 = 0.f, p4 = 0.f;   // own image's moments

    int u = slot * RUQ + min(slot, RUR);
    const int uend = u + RUQ + (slot < RUR ? 1 : 0);

    const float4 z4 = make_float4(0.f, 0.f, 0.f, 0.f);

    while (u < uend) {
        const int scol  = u >> 9;            // 0..255
        const int ra    = u & 511;
        const int n     = min(uend - u, HH - ra);
        const int img   = scol >> 3;
        const int strip = scol & 7;          // 8 strips of 64 cols
        const int cb    = (strip << 6) + sub * 4;
        const bool hload =
            (sub == 0) ? (strip > 0) : ((sub == 15) ? (strip < 7) : false);

        const size_t base = (size_t)img * (HH * WW) + (size_t)ra * WW + cb;
        const float* pim = (half ? g_out : g_in) + base;   // my image, row r
        const float* pm  = g_mask + base;

        // ---- prime: rows ra-1, ra, ra+1 + mask row ra ----
        float P0[6], P1[6], P2[6];
        ldrow(P0, pim - WW, ra - 1, sub, eo, hload);
        ldrow(P1, pim,      ra,     sub, eo, hload);
        ldrow(P2, pim + WW, ra + 1, sub, eo, hload);
        float4 Mcur = *(const float4*)pm;
        int r = ra;

#define STEP(A, B, C)                                                        \
    do {                                                                     \
        float F[6];                                                          \
        ldrow(F, pim + 2 * WW, r + 2, sub, eo, hload);                       \
        float4 mnx = ((unsigned)(r + 1) < (unsigned)HH)                      \
                         ? *(const float4*)(pm + WW) : z4;                   \
        float var[4], lap[4];                                                \
        proc6(P##A, P##B, P##C, var, lap);                                   \
        float mv[4] = { Mcur.x, Mcur.y, Mcur.z, Mcur.w };                    \
        _Pragma("unroll")                                                    \
        for (int j = 0; j < 4; j++) {                                        \
            float m = mv[j];                                                 \
            msum += m;                                                       \
            float x = P##B[j];                                               \
            float x2 = x * x, qx = x2 * m;                                   \
            p1 = fmaf(x, m, p1);  p2 += qx;                                  \
            p3 = fmaf(x, qx, p3); p4 = fmaf(x2, qx, p4);                     \
            float vq = __shfl_xor_sync(FULLM, var[j], 16);                   \
            float lq = __shfl_xor_sync(FULLM, lap[j], 16);                   \
            texs = fmaf(fabsf(var[j] - vq), m, texs);                        \
            shps = fmaf(fabsf(lap[j] - lq), m, shps);                        \
        }                                                                    \
        _Pragma("unroll")                                                    \
        for (int j = 0; j < 6; j++) P##A[j] = F[j];                          \
        Mcur = mnx;                                                          \
        pim += WW; pm += WW; r++;                                            \
    } while (0)

        int k = 0;
        while (k + 3 <= n) { STEP(0, 1, 2); STEP(1, 2, 0); STEP(2, 0, 1); k += 3; }
        if (k < n) { STEP(0, 1, 2); k++; }
        if (k < n) { STEP(1, 2, 0); k++; }
#undef STEP

        u += n;
    }

    // ---- warp reduction ----
    // full-warp sums (double-counted across halves -> x0.5):
    #pragma unroll
    for (int off = 16; off; off >>= 1) {
        msum += __shfl_xor_sync(FULLM, msum, off);
        texs += __shfl_xor_sync(FULLM, texs, off);
        shps += __shfl_xor_sync(FULLM, shps, off);
    }
    // half-warp sums (per-image moments): lane 0 / lane 16 hold results
    #pragma unroll
    for (int off = 8; off; off >>= 1) {
        p1 += __shfl_xor_sync(FULLM, p1, off);
        p2 += __shfl_xor_sync(FULLM, p2, off);
        p3 += __shfl_xor_sync(FULLM, p3, off);
        p4 += __shfl_xor_sync(FULLM, p4, off);
    }
    if (lane == 0) {
        sred[0][wid]  = msum * 0.5f;
        sred[9][wid]  = texs * 0.5f;
        sred[10][wid] = shps * 0.5f;
        sred[1][wid] = p1; sred[2][wid] = p2;
        sred[3][wid] = p3; sred[4][wid] = p4;
    }
    if (lane == 16) {
        sred[5][wid] = p1; sred[6][wid] = p2;
        sred[7][wid] = p3; sred[8][wid] = p4;
    }
    __syncthreads();
    if (t < 11) {
        double s = 0.0;
        #pragma unroll
        for (int w = 0; w < 8; w++) s += (double)sred[t][w];
        g_part[blockIdx.x][t] = s;
    }

    // ---- last-block finalize ----
    __threadfence();
    if (t == 0) {
        unsigned prev = atomicAdd(&g_cnt, 1u);
        s_last = (prev == NBLK - 1);
    }
    __syncthreads();
    if (!s_last) return;

    for (int k = wid; k < 11; k += 8) {
        double s = 0.0;
        for (int b = lane; b < NBLK; b += 32)
            s += g_part[b][k];
        #pragma unroll
        for (int off = 16; off; off >>= 1)
            s += __shfl_xor_sync(FULLM, s, off);
        if (lane == 0) sacc[k] = s;
    }
    __syncthreads();

    if (t == 0) {
        g_cnt = 0;   // reset for next graph replay
        const double EPS = 1e-8;
        const double NTOT = (double)BB * HH * WW;

        double M0 = sacc[0];
        double ms = M0 + EPS;
        double Mi1 = sacc[1], Mi2 = sacc[2], Mi3 = sacc[3], Mi4 = sacc[4];
        double Mo1 = sacc[5], Mo2 = sacc[6], Mo3 = sacc[7], Mo4 = sacc[8];

        double im = Mi1 / ms, om = Mo1 / ms;
        double im2 = im * im, om2 = om * om;

        double c2i = Mi2 - 2.0 * im * Mi1 + im2 * M0;
        double c3i = Mi3 - 3.0 * im * Mi2 + 3.0 * im2 * Mi1 - im2 * im * M0;
        double c4i = Mi4 - 4.0 * im * Mi3 + 6.0 * im2 * Mi2 - 4.0 * im2 * im * Mi1 + im2 * im2 * M0;

        double c2o = Mo2 - 2.0 * om * Mo1 + om2 * M0;
        double c3o = Mo3 - 3.0 * om * Mo2 + 3.0 * om2 * Mo1 - om2 * om * M0;
        double c4o = Mo4 - 4.0 * om * Mo3 + 6.0 * om2 * Mo2 - 4.0 * om2 * om * Mo1 + om2 * om2 * M0;

        double iv = c2i / ms, ov = c2o / ms;
        double isk = c3i / (ms * (iv * sqrt(iv) + EPS));
        double osk = c3o / (ms * (ov * sqrt(ov) + EPS));
        double iku = c4i / (ms * (iv * iv + EPS));
        double oku = c4o / (ms * (ov * ov + EPS));

        double dm = im - om, dv = iv - ov, dsk = isk - osk, dku = iku - oku;
        double inten = dm * dm + dv * dv + dsk * dsk + dku * dku;
        double tex = sacc[9]  / NTOT;
        double shp = sacc[10] / NTOT;
        double total = inten + tex + 0.5 * shp;

        final_out[0] = (float)inten;
        final_out[1] = (float)tex;
        final_out[2] = (float)shp;
        final_out[3] = (float)total;
    }
}

extern "C" void kernel_launch(void* const* d_in, const int* in_sizes, int n_in,
                              void* d_out, int out_size) {
    const float* in_img  = (const float*)d_in[0];
    const float* out_img = (const float*)d_in[1];
    const float* mask    = (const float*)d_in[2];

    k_main<<<NBLK, NTHR>>>(in_img, out_img, mask, (float*)d_out);
}

// round 13
// speedup vs baseline: 1.0494x; 1.0494x over previous
#include <cuda_runtime.h>
#include <math.h>

// ---------------------------------------------------------------------------
// RadiomicsPreservationLoss — smem-tiled stencil.
// Per tile (16 rows x 128 cols of one image-strip): block cooperatively loads
// an 18x130 halo tile of BOTH images into smem (each global row loaded ONCE,
// coalesced float4), one sync, then 8 warps compute 2 rows each from smem:
// no shuffles, no halo predicates, no boundary SELs in the hot loop.
// Mask is a direct coalesced LDG. occ-3, 444 blocks, fused finalize.
// inputs: input_img, output_img, roi_mask  [32,1,512,512] f32
// output: [intensity, texture, shape, total] (4 x f32)
// ---------------------------------------------------------------------------

#define HH 512
#define WW 512
#define BB 32
#define NBLK 444                 // 3 blocks/SM
#define NTHR 256
#define NTILE 4096               // 32 img * 4 strips * 32 tiles of 16 rows
#define TR 16                    // output rows per tile
#define SR 18                    // smem rows (halo)
#define SSTR 132                 // smem row stride (floats): 0..127 own,
                                 // 128 right halo, 130 left halo, 129/131 pad
#define FULLM 0xffffffffu

__device__ double g_part[NBLK][11];
__device__ unsigned g_cnt = 0;

// 3x3 variance, laplacian, center for 4 px from three 6-wide rows.
// Layout: [0..3]=own cols, [4]=left halo, [5]=right halo.
__device__ __forceinline__ void proc6(
    const float* __restrict__ A0, const float* __restrict__ A1,
    const float* __restrict__ A2,
    float* __restrict__ var, float* __restrict__ lap, float* __restrict__ cen)
{
    float cs[6], cq[6];
    #pragma unroll
    for (int j = 0; j < 6; j++) {
        cs[j] = A0[j] + A1[j] + A2[j];
        float u = A0[j] * A0[j];
        u = fmaf(A1[j], A1[j], u);
        cq[j] = fmaf(A2[j], A2[j], u);
    }
    const float inv9 = 1.f / 9.f;
    #pragma unroll
    for (int p = 0; p < 4; p++) {
        float Sm = (p == 0) ? cs[4] : cs[p - 1];
        float Sp = (p == 3) ? cs[5] : cs[p + 1];
        float Qm = (p == 0) ? cq[4] : cq[p - 1];
        float Qp = (p == 3) ? cq[5] : cq[p + 1];
        float S = Sm + cs[p] + Sp;
        float Q = Qm + cq[p] + Qp;
        float bmn = S * inv9;
        var[p] = fmaf(-bmn, bmn, Q * inv9);
        float am = (p == 0) ? A1[4] : A1[p - 1];
        float ap = (p == 3) ? A1[5] : A1[p + 1];
        lap[p] = fmaf(-5.f, A1[p], cs[p] + am + ap);
        cen[p] = A1[p];
    }
}

// Read 6 neighborhood values of one smem row for this lane.
__device__ __forceinline__ void rd6s(
    float* __restrict__ R, const float* __restrict__ row, int l4, int loff)
{
    float4 q = *(const float4*)(row + l4);
    R[0] = q.x; R[1] = q.y; R[2] = q.z; R[3] = q.w;
    R[4] = row[loff];
    R[5] = row[l4 + 4];
}

__global__ void __launch_bounds__(NTHR, 3) k_main(
    const float* __restrict__ g_in,
    const float* __restrict__ g_out,
    const float* __restrict__ g_mask,
    float* __restrict__ final_out)
{
    __shared__ float tile[2][SR * SSTR];     // [img][row*132+col]
    __shared__ float sred[11][8];
    __shared__ bool s_last;
    __shared__ double sacc[11];

    const int t    = threadIdx.x;
    const int lane = t & 31;
    const int wid  = t >> 5;
    const int l4   = lane << 2;
    const int loff = (lane == 0) ? 130 : (l4 - 1);

    float msum = 0.f;
    float xi1 = 0.f, xi2 = 0.f, xi3 = 0.f, xi4 = 0.f;
    float yo1 = 0.f, yo2 = 0.f, yo3 = 0.f, yo4 = 0.f;
    float texs = 0.f, shps = 0.f;

    for (int tl = blockIdx.x; tl < NTILE; tl += NBLK) {
        const int img   = tl >> 7;           // 128 tiles per image
        const int rest  = tl & 127;
        const int strip = rest & 3;
        const int tr    = rest >> 2;         // 0..31
        const int r0    = tr * TR;
        const int c0    = strip << 7;
        const size_t ib = (size_t)img * (HH * WW);
        const float* gi = g_in  + ib;
        const float* go = g_out + ib;

        __syncthreads();   // prior tile's compute done before overwrite

        // ---- cooperative load: 18 rows x 32 float4 x 2 images ----
        #pragma unroll
        for (int it = 0; it < 5; it++) {
            int i = t + it * NTHR;
            if (i < 2 * SR * 32) {
                int img2 = (i >= SR * 32);
                int j    = i - img2 * (SR * 32);
                int rr   = j >> 5;
                int c4   = (j & 31) << 2;
                int grow = r0 - 1 + rr;
                float4 v = make_float4(0.f, 0.f, 0.f, 0.f);
                if ((unsigned)grow < (unsigned)HH) {
                    const float* src = (img2 ? go : gi) + grow * WW + c0 + c4;
                    v = *(const float4*)src;
                }
                *(float4*)&tile[img2][rr * SSTR + c4] = v;
            }
        }
        // ---- halo scalars: 18 rows x 2 sides x 2 images = 72 ----
        if (t < 72) {
            int img2 = (t >= 36);
            int j    = t - img2 * 36;
            int rr   = j >> 1;
            int side = j & 1;
            int grow = r0 - 1 + rr;
            int gcol = c0 + (side ? 128 : -1);
            float v = 0.f;
            if ((unsigned)grow < (unsigned)HH && (unsigned)gcol < (unsigned)WW)
                v = (img2 ? go : gi)[grow * WW + gcol];
            tile[img2][rr * SSTR + (side ? 128 : 130)] = v;
        }
        __syncthreads();

        // ---- compute: warp w handles rows r0+2w, r0+2w+1 ----
        const float* pm = g_mask + ib + (size_t)(r0 + 2 * wid) * WW + c0 + l4;

        #pragma unroll
        for (int s = 0; s < 2; s++) {
            const int rr = 2 * wid + s + 1;        // smem row of output row
            float4 m0 = *(const float4*)(pm + s * WW);

            float A0[6], A1[6], A2[6];
            float vi[4], li[4], xc[4];
            rd6s(A0, &tile[0][(rr - 1) * SSTR], l4, loff);
            rd6s(A1, &tile[0][ rr      * SSTR], l4, loff);
            rd6s(A2, &tile[0][(rr + 1) * SSTR], l4, loff);
            proc6(A0, A1, A2, vi, li, xc);

            float vo[4], lo[4], yc[4];
            rd6s(A0, &tile[1][(rr - 1) * SSTR], l4, loff);
            rd6s(A1, &tile[1][ rr      * SSTR], l4, loff);
            rd6s(A2, &tile[1][(rr + 1) * SSTR], l4, loff);
            proc6(A0, A1, A2, vo, lo, yc);

            float mv[4] = { m0.x, m0.y, m0.z, m0.w };
            #pragma unroll
            for (int j = 0; j < 4; j++) {
                float m = mv[j];
                msum += m;
                float x = xc[j], y = yc[j];
                float x2 = x * x, y2 = y * y;
                float qx = x2 * m, qy = y2 * m;
                xi1 = fmaf(x, m, xi1);  xi2 += qx;
                xi3 = fmaf(x, qx, xi3); xi4 = fmaf(x2, qx, xi4);
                yo1 = fmaf(y, m, yo1);  yo2 += qy;
                yo3 = fmaf(y, qy, yo3); yo4 = fmaf(y2, qy, yo4);
                texs = fmaf(fabsf(vo[j] - vi[j]), m, texs);
                shps = fmaf(fabsf(lo[j] - li[j]), m, shps);
            }
        }
    }

    // ---- block reduction -> fp64 partial ----
    float acc[11] = { msum, xi1, xi2, xi3, xi4, yo1, yo2, yo3, yo4, texs, shps };
    #pragma unroll
    for (int k = 0; k < 11; k++) {
        float v = acc[k];
        #pragma unroll
        for (int off = 16; off; off >>= 1)
            v += __shfl_xor_sync(FULLM, v, off);
        if (lane == 0) sred[k][wid] = v;
    }
    __syncthreads();
    if (t < 11) {
        double s = 0.0;
        #pragma unroll
        for (int w = 0; w < 8; w++) s += (double)sred[t][w];
        g_part[blockIdx.x][t] = s;
    }

    // ---- last-block finalize ----
    __threadfence();
    if (t == 0) {
        unsigned prev = atomicAdd(&g_cnt, 1u);
        s_last = (prev == NBLK - 1);
    }
    __syncthreads();
    if (!s_last) return;

    for (int k = wid; k < 11; k += 8) {
        double s = 0.0;
        for (int b = lane; b < NBLK; b += 32)
            s += g_part[b][k];
        #pragma unroll
        for (int off = 16; off; off >>= 1)
            s += __shfl_xor_sync(FULLM, s, off);
        if (lane == 0) sacc[k] = s;
    }
    __syncthreads();

    if (t == 0) {
        g_cnt = 0;   // reset for next graph replay
        const double EPS = 1e-8;
        const double NTOT = (double)BB * HH * WW;

        double M0 = sacc[0];
        double ms = M0 + EPS;
        double Mi1 = sacc[1], Mi2 = sacc[2], Mi3 = sacc[3], Mi4 = sacc[4];
        double Mo1 = sacc[5], Mo2 = sacc[6], Mo3 = sacc[7], Mo4 = sacc[8];

        double im = Mi1 / ms, om = Mo1 / ms;
        double im2 = im * im, om2 = om * om;

        double c2i = Mi2 - 2.0 * im * Mi1 + im2 * M0;
        double c3i = Mi3 - 3.0 * im * Mi2 + 3.0 * im2 * Mi1 - im2 * im * M0;
        double c4i = Mi4 - 4.0 * im * Mi3 + 6.0 * im2 * Mi2 - 4.0 * im2 * im * Mi1 + im2 * im2 * M0;

        double c2o = Mo2 - 2.0 * om * Mo1 + om2 * M0;
        double c3o = Mo3 - 3.0 * om * Mo2 + 3.0 * om2 * Mo1 - om2 * om * M0;
        double c4o = Mo4 - 4.0 * om * Mo3 + 6.0 * om2 * Mo2 - 4.0 * om2 * om * Mo1 + om2 * om2 * M0;

        double iv = c2i / ms, ov = c2o / ms;
        double isk = c3i / (ms * (iv * sqrt(iv) + EPS));
        double osk = c3o / (ms * (ov * sqrt(ov) + EPS));
        double iku = c4i / (ms * (iv * iv + EPS));
        double oku = c4o / (ms * (ov * ov + EPS));

        double dm = im - om, dv = iv - ov, dsk = isk - osk, dku = iku - oku;
        double inten = dm * dm + dv * dv + dsk * dsk + dku * dku;
        double tex = sacc[9]  / NTOT;
        double shp = sacc[10] / NTOT;
        double total = inten + tex + 0.5 * shp;

        final_out[0] = (float)inten;
        final_out[1] = (float)tex;
        final_out[2] = (float)shp;
        final_out[3] = (float)total;
    }
}

extern "C" void kernel_launch(void* const* d_in, const int* in_sizes, int n_in,
                              void* d_out, int out_size) {
    const float* in_img  = (const float*)d_in[0];
    const float* out_img = (const float*)d_in[1];
    const float* mask    = (const float*)d_in[2];

    k_main<<<NBLK, NTHR>>>(in_img, out_img, mask, (float*)d_out);
}